// round 2
// baseline (speedup 1.0000x reference)
#include <cuda_runtime.h>

// IndRNN, 2 layers fused: per channel c=(b,h):
//   s0 = relu(x[t,c] + w0[h]*s0);  s1 = relu(s0 + w1[h]*s1);  out[t,c] = s1
// One thread per channel, software-pipelined double-buffered loads over t.

#define T_STEPS 2048
#define BATCH   32
#define HID     512
#define CHAN    (BATCH * HID)   // 16384
#define U       16              // chunk size (time steps per buffer)

__global__ __launch_bounds__(32) void indrnn_fused_kernel(
    const float* __restrict__ x,      // [T, B, H]
    const float* __restrict__ w_hh,   // [2, H]
    const float* __restrict__ h0,     // [2, B, H]
    float* __restrict__ out)          // [T, B, H]
{
    const int c = blockIdx.x * 32 + threadIdx.x;   // channel in [0, 16384)
    const int h = c & (HID - 1);

    const float w0 = w_hh[h];
    const float w1 = w_hh[HID + h];
    float s0 = h0[c];
    float s1 = h0[CHAN + c];

    const float* xp = x + c;
    float*       op = out + c;

    float bufA[U], bufB[U];

    // Preload chunk 0 into bufA.
#pragma unroll
    for (int u = 0; u < U; ++u)
        bufA[u] = __ldcs(xp + (size_t)u * CHAN);

    // Process chunk pairs: while computing one buffer, loads for the
    // other are in flight (up to 32 outstanding LDGs per thread-warp).
    for (int t0 = 0; t0 < T_STEPS; t0 += 2 * U) {
        const int tB = t0 + U;  // always < T (T multiple of 2U)

        // Prefetch chunk B.
#pragma unroll
        for (int u = 0; u < U; ++u)
            bufB[u] = __ldcs(xp + (size_t)(tB + u) * CHAN);

        // Compute + store chunk A.
#pragma unroll
        for (int u = 0; u < U; ++u) {
            s0 = fmaxf(fmaf(s0, w0, bufA[u]), 0.0f);
            s1 = fmaxf(fmaf(s1, w1, s0), 0.0f);
            __stcs(op + (size_t)(t0 + u) * CHAN, s1);
        }

        // Prefetch next chunk A (clamped on the final iteration; those
        // values are never consumed, the load just stays in-bounds).
        const int tA  = t0 + 2 * U;
        const int tAc = (tA < T_STEPS) ? tA : 0;
#pragma unroll
        for (int u = 0; u < U; ++u)
            bufA[u] = __ldcs(xp + (size_t)(tAc + u) * CHAN);

        // Compute + store chunk B.
#pragma unroll
        for (int u = 0; u < U; ++u) {
            s0 = fmaxf(fmaf(s0, w0, bufB[u]), 0.0f);
            s1 = fmaxf(fmaf(s1, w1, s0), 0.0f);
            __stcs(op + (size_t)(tB + u) * CHAN, s1);
        }
    }
}

extern "C" void kernel_launch(void* const* d_in, const int* in_sizes, int n_in,
                              void* d_out, int out_size)
{
    const float* x    = (const float*)d_in[0];  // [2048, 32, 512]
    const float* w_hh = (const float*)d_in[1];  // [2, 512]
    const float* h0   = (const float*)d_in[2];  // [2, 32, 512]
    float*       out  = (float*)d_out;          // [2048, 32, 512]

    (void)in_sizes; (void)n_in; (void)out_size;

    // 16384 channels / 32 threads = 512 blocks (balances 3-4 warps/SM).
    indrnn_fused_kernel<<<512, 32>>>(x, w_hh, h0, out);
}